// round 17
// baseline (speedup 1.0000x reference)
#include <cuda_runtime.h>
#include <cuda_fp16.h>
#include <math.h>
#include <stdint.h>

// Problem constants
#define B   16
#define C   384
#define HD  8
#define DC  48
#define HW  4096
#define QC  192
#define KVC 768

#define NCHUNK_QK 8
#define NCHUNK_SV 16

// Scratch (device globals)
__device__ float g_Sp [NCHUNK_QK * B * HD * DC * DC];
__device__ float g_ssp[NCHUNK_QK * B * HD * 2 * DC];

// fp16 operand buffers (ALL 1-limb)
__device__ __half g_wkv[KVC * C];
__device__ __half g_wq [C * QC];
__device__ __half g_wp [C * C];
__device__ __half g_xh [(long long)B * C  * HW];
__device__ __half g_qrh[(long long)B * QC * HW];
__device__ __half g_kvh[(long long)B * KVC * HW];
__device__ __half g_qh [(long long)B * C  * HW];
__device__ __half g_oh [(long long)B * C  * HW];
__device__ __half g_Sh [B * HD * DC * DC];

// ---------------------------------------------------------------------------
// PTX helpers
// ---------------------------------------------------------------------------
__device__ __forceinline__ uint32_t smem_u32(const void* p) {
    uint32_t a;
    asm("{ .reg .u64 t; cvta.to.shared.u64 t, %1; cvt.u32.u64 %0, t; }" : "=r"(a) : "l"(p));
    return a;
}
__device__ __forceinline__ void cp16(uint32_t dst, const void* src) {
    asm volatile("cp.async.ca.shared.global [%0], [%1], 16;" :: "r"(dst), "l"(src));
}
#define CP_COMMIT() asm volatile("cp.async.commit_group;" ::: "memory")
#define CP_WAIT0()  asm volatile("cp.async.wait_group 0;" ::: "memory")
#define CP_WAIT1()  asm volatile("cp.async.wait_group 1;" ::: "memory")
#define CP_WAIT2()  asm volatile("cp.async.wait_group 2;" ::: "memory")

__device__ __forceinline__ void ldsm_x4(uint32_t r[4], uint32_t addr) {
    asm volatile("ldmatrix.sync.aligned.m8n8.x4.shared.b16 {%0,%1,%2,%3}, [%4];"
                 : "=r"(r[0]), "=r"(r[1]), "=r"(r[2]), "=r"(r[3]) : "r"(addr));
}
__device__ __forceinline__ void ldsm_x4_t(uint32_t r[4], uint32_t addr) {
    asm volatile("ldmatrix.sync.aligned.m8n8.x4.trans.shared.b16 {%0,%1,%2,%3}, [%4];"
                 : "=r"(r[0]), "=r"(r[1]), "=r"(r[2]), "=r"(r[3]) : "r"(addr));
}
__device__ __forceinline__ void mma_f16(float* c, const uint32_t a[4],
                                        uint32_t b0, uint32_t b1) {
    asm volatile(
        "mma.sync.aligned.m16n8k16.row.col.f32.f16.f16.f32 "
        "{%0,%1,%2,%3}, {%4,%5,%6,%7}, {%8,%9}, {%0,%1,%2,%3};"
        : "+f"(c[0]), "+f"(c[1]), "+f"(c[2]), "+f"(c[3])
        : "r"(a[0]), "r"(a[1]), "r"(a[2]), "r"(a[3]), "r"(b0), "r"(b1));
}

__device__ __forceinline__ uint32_t pack_h2(float x0, float x1) {
    return (uint32_t)__half_as_ushort(__float2half_rn(x0))
         | ((uint32_t)__half_as_ushort(__float2half_rn(x1)) << 16);
}
__device__ __forceinline__ float h_lo(uint32_t v) {
    return __half2float(__ushort_as_half((uint16_t)v));
}
__device__ __forceinline__ float h_hi(uint32_t v) {
    return __half2float(__ushort_as_half((uint16_t)(v >> 16)));
}

// fp32 -> fp16 (round-to-nearest), 4 elems/thread
__global__ __launch_bounds__(256) void split1_kernel(
    const float* __restrict__ src, __half* __restrict__ dh, int n4)
{
    int i = blockIdx.x * 256 + threadIdx.x;
    if (i < n4) {
        float4 v = ((const float4*)src)[i];
        ((uint2*)dh)[i] = make_uint2(pack_h2(v.x, v.y), pack_h2(v.z, v.w));
    }
}

// ---------------------------------------------------------------------------
// fp16 1-term tensor-core GEMM: Out[b][j][s] = sum_k W[j][k] * Act[b][k][s]
// CTA tile 128(j) x 128(s), K-chunk 64, 8 warps (4m x 2n), 3-stage pipeline.
// HALF_OUT: coalesced fp16 stores via smem bounce; else fp32 direct.
// ---------------------------------------------------------------------------
#define WPITCH 72                    // 64 + 8 pad (144B rows, conflict-free ldsm)
#define APITCH 136
#define WTE (128 * WPITCH)           // 9216
#define ATE (64 * APITCH)            // 8704
#define BUFE (WTE + ATE)             // 17920
#define NSTAGE 3
#define SMEM_BYTES (NSTAGE * BUFE * 2)   // 107520 bytes
#define EPITCH 136                   // epilogue bounce pitch (halves)

template<int K, bool HALF_OUT>
__global__ __launch_bounds__(256, 2) void gemm_db_kernel(
    const __half* __restrict__ W,
    const __half* __restrict__ Ax,
    float* __restrict__ Of,
    __half* __restrict__ Oh,
    int OCtot)
{
    extern __shared__ __align__(16) uint16_t dynsmem[];
    const uint32_t uS = smem_u32(dynsmem);

    const int tid  = threadIdx.x;
    const int warp = tid >> 5;
    const int lane = tid & 31;
    const int s0 = blockIdx.x * 128;
    const int j0 = blockIdx.y * 128;
    const int b  = blockIdx.z;

    const __half* Ap = Ax + (long long)b * K * HW;
    const long long obase = ((long long)b * OCtot + j0) * HW + s0;

    const int mbase = (warp >> 1) * 32;
    const int nbase = (warp & 1) * 64;

    float acc[64];
    #pragma unroll
    for (int i = 0; i < 64; i++) acc[i] = 0.f;

    const int lrow  = (lane & 7) + ((lane >> 3) & 1) * 8;
    const int lhalf = lane >> 4;

    auto stage = [&](int kc, int buf) {
        const uint32_t bW = uS + (uint32_t)(buf * BUFE) * 2;
        const uint32_t bA = bW + WTE * 2;
        const int k0 = kc * 64;
        #pragma unroll
        for (int i = 0; i < 4; i++) {
            int idx = i * 256 + tid;
            int j = idx >> 3, q = idx & 7;
            uint32_t d = (uint32_t)(j * WPITCH + q * 8) * 2;
            cp16(bW + d, W + (long long)(j0 + j) * K + k0 + q * 8);
        }
        #pragma unroll
        for (int i = 0; i < 4; i++) {
            int idx = i * 256 + tid;
            int kk = idx >> 4, g = idx & 15;
            uint32_t d = (uint32_t)(kk * APITCH + g * 8) * 2;
            cp16(bA + d, Ap + (long long)(k0 + kk) * HW + s0 + g * 8);
        }
        CP_COMMIT();
    };

    const int NK = K / 64;
    stage(0, 0);
    if (NK > 1) stage(1, 1);

    for (int kc = 0; kc < NK; kc++) {
        if (kc + 2 < NK) {
            stage(kc + 2, (kc + 2) % NSTAGE);
            CP_WAIT2();
        } else if (kc + 1 < NK) {
            CP_WAIT1();
        } else {
            CP_WAIT0();
        }
        __syncthreads();

        const int buf = kc % NSTAGE;
        const uint32_t bW = uS + (uint32_t)(buf * BUFE) * 2;
        const uint32_t bA = bW + WTE * 2;

        #pragma unroll
        for (int kh = 0; kh < 4; kh++) {
            uint32_t ah[2][4];
            #pragma unroll
            for (int mt = 0; mt < 2; mt++) {
                uint32_t off = (uint32_t)((mbase + mt * 16 + lrow) * (WPITCH * 2)
                                          + kh * 32 + lhalf * 16);
                ldsm_x4(ah[mt], bW + off);
            }
            #pragma unroll
            for (int np = 0; np < 4; np++) {
                uint32_t boff = (uint32_t)((kh * 16 + lrow) * (APITCH * 2)
                                           + (nbase + np * 16 + lhalf * 8) * 2);
                uint32_t bf[4];
                ldsm_x4_t(bf, bA + boff);
                #pragma unroll
                for (int nt2 = 0; nt2 < 2; nt2++) {
                    const uint32_t b0 = bf[nt2 * 2], b1 = bf[nt2 * 2 + 1];
                    const int nt = np * 2 + nt2;
                    #pragma unroll
                    for (int mt = 0; mt < 2; mt++)
                        mma_f16(acc + (mt * 8 + nt) * 4, ah[mt], b0, b1);
                }
            }
        }
        __syncthreads();
    }

    // ---- epilogue ----
    const int crow = lane >> 2;
    const int ccol = (lane & 3) * 2;
    if (HALF_OUT) {
        // bounce through smem (conflict-free), then coalesced 16B stores
        #pragma unroll
        for (int mt = 0; mt < 2; mt++) {
            #pragma unroll
            for (int nt = 0; nt < 8; nt++) {
                const float* cp = acc + (mt * 8 + nt) * 4;
                int r0 = mbase + mt * 16 + crow;
                int cc = nbase + nt * 8 + ccol;
                *(uint32_t*)&dynsmem[r0 * EPITCH + cc]       = pack_h2(cp[0], cp[1]);
                *(uint32_t*)&dynsmem[(r0 + 8) * EPITCH + cc] = pack_h2(cp[2], cp[3]);
            }
        }
        __syncthreads();
        #pragma unroll
        for (int i = 0; i < 8; i++) {
            int idx = i * 256 + tid;          // 128 rows x 16 segs
            int row = idx >> 4, seg = idx & 15;
            uint4 v = *(uint4*)&dynsmem[row * EPITCH + seg * 8];
            *(uint4*)&Oh[obase + (long long)row * HW + seg * 8] = v;
        }
    } else {
        #pragma unroll
        for (int mt = 0; mt < 2; mt++) {
            #pragma unroll
            for (int nt = 0; nt < 8; nt++) {
                const float* cp = acc + (mt * 8 + nt) * 4;
                long long r0 = obase + (long long)(mbase + mt * 16 + crow) * HW
                             + nbase + nt * 8 + ccol;
                *(float2*)&Of[r0]          = make_float2(cp[0], cp[1]);
                *(float2*)&Of[r0 + 8 * HW] = make_float2(cp[2], cp[3]);
            }
        }
    }
}

// ---------------------------------------------------------------------------
// qk_mma: S_partial = Q K^T over a 512-spatial slice (fp16 1-term MMA)
// + per-row sumsq partials (from the same rounded values the MMA uses).
// grid = (NCHUNK_QK, B*HD), 256 threads.
// ---------------------------------------------------------------------------
#define QKP 136
#define QK_ARR (48 * QKP)
#define QK_SMEM (2 * QK_ARR * 2)     // 26112 bytes

__global__ __launch_bounds__(256) void qk_mma_kernel(
    const __half* __restrict__ qh, const __half* __restrict__ kh,
    float* __restrict__ Sp, float* __restrict__ ssp)
{
    extern __shared__ __align__(16) uint16_t dynsmem[];
    __shared__ float Sred[DC][DC + 1];

    const uint32_t uQ = smem_u32(dynsmem);
    const uint32_t uK = uQ + QK_ARR * 2;

    const int chunk = blockIdx.x;
    const int bh = blockIdx.y;
    const int b  = bh >> 3;
    const int h  = bh & 7;
    const long long qbase = ((long long)b * C   + h * DC) * HW;
    const long long kbase = ((long long)b * KVC + h * DC) * HW;
    const int sbase = chunk * (HW / NCHUNK_QK);

    const int tid  = threadIdx.x;
    const int warp = tid >> 5;
    const int lane = tid & 31;
    const int lrow  = (lane & 7) + ((lane >> 3) & 1) * 8;
    const int lhalf = lane >> 4;
    const int brow = ((lane >> 4) << 3) + (lane & 7);
    const int bcol = ((lane >> 3) & 1) * 8;

    const int kcol = warp * 16;

    float acc[72];
    #pragma unroll
    for (int i = 0; i < 72; i++) acc[i] = 0.f;
    float ssq = 0.f;

    for (int it = 0; it < 4; it++) {
        const int s0 = sbase + it * 128;
        #pragma unroll
        for (int i = 0; i < 3; i++) {
            int idx = i * 256 + tid;
            int row = idx >> 4, g = idx & 15;
            uint32_t d = (uint32_t)(row * QKP + g * 8) * 2;
            cp16(uQ + d, qh + qbase + (long long)row * HW + s0 + g * 8);
            cp16(uK + d, kh + kbase + (long long)row * HW + s0 + g * 8);
        }
        CP_COMMIT();
        CP_WAIT0();
        __syncthreads();

        uint32_t bhf[12];
        #pragma unroll
        for (int g = 0; g < 3; g++) {
            uint32_t off = (uint32_t)((g * 16 + brow) * QKP + kcol + bcol) * 2;
            ldsm_x4(&bhf[g * 4], uK + off);
        }
        #pragma unroll
        for (int mt = 0; mt < 3; mt++) {
            uint32_t ah[4];
            uint32_t off = (uint32_t)((mt * 16 + lrow) * QKP + kcol + lhalf * 8) * 2;
            ldsm_x4(ah, uQ + off);
            #pragma unroll
            for (int n8 = 0; n8 < 6; n8++)
                mma_f16(acc + (mt * 6 + n8) * 4, ah, bhf[n8 * 2], bhf[n8 * 2 + 1]);
        }

        if (tid < 2 * DC) {
            const int r = (tid < DC) ? tid : tid - DC;
            const uint16_t* ph = (const uint16_t*)dynsmem
                               + (tid < DC ? 0 : QK_ARR) + r * QKP;
            #pragma unroll 8
            for (int g = 0; g < 64; g++) {
                uint32_t v = *(const uint32_t*)(ph + g * 2);
                float a = h_lo(v);
                float c = h_hi(v);
                ssq = fmaf(a, a, ssq);
                ssq = fmaf(c, c, ssq);
            }
        }
        __syncthreads();
    }

    for (int i = tid; i < DC * DC; i += 256) Sred[i / DC][i % DC] = 0.f;
    __syncthreads();
    const int crow = lane >> 2;
    const int ccol = (lane & 3) * 2;
    #pragma unroll
    for (int mt = 0; mt < 3; mt++) {
        #pragma unroll
        for (int n8 = 0; n8 < 6; n8++) {
            const float* cp = acc + (mt * 6 + n8) * 4;
            int r0 = mt * 16 + crow, c0 = n8 * 8 + ccol;
            atomicAdd(&Sred[r0][c0],     cp[0]);
            atomicAdd(&Sred[r0][c0 + 1], cp[1]);
            atomicAdd(&Sred[r0 + 8][c0],     cp[2]);
            atomicAdd(&Sred[r0 + 8][c0 + 1], cp[3]);
        }
    }
    __syncthreads();

    float* Sout = Sp + ((long long)chunk * (B * HD) + bh) * (DC * DC);
    for (int i = tid; i < DC * DC; i += 256)
        Sout[i] = Sred[i / DC][i % DC];
    if (tid < 2 * DC)
        ssp[((long long)chunk * (B * HD) + bh) * (2 * DC) + tid] = ssq;
}

// ---------------------------------------------------------------------------
// Reduce partials, norms + temperature, softmax; write S as fp16 (1-limb).
// ---------------------------------------------------------------------------
__global__ __launch_bounds__(256) void softmax_kernel(
    const float* __restrict__ Sp, const float* __restrict__ ssp,
    const float* __restrict__ temperature,
    __half* __restrict__ ShG)
{
    const int bh = blockIdx.x;
    const int h  = bh & 7;
    const int tid = threadIdx.x;

    __shared__ float S[DC][DC + 1];
    __shared__ float invq[DC], invk[DC];

    for (int i = tid; i < DC * DC; i += 256) {
        float s = 0.f;
        #pragma unroll
        for (int ch = 0; ch < NCHUNK_QK; ch++)
            s += Sp[((long long)ch * (B * HD) + bh) * (DC * DC) + i];
        S[i / DC][i % DC] = s;
    }
    if (tid < 2 * DC) {
        float s = 0.f;
        #pragma unroll
        for (int ch = 0; ch < NCHUNK_QK; ch++)
            s += ssp[((long long)ch * (B * HD) + bh) * (2 * DC) + tid];
        float inv = 1.0f / fmaxf(sqrtf(s), 1e-12f);
        if (tid < DC) invq[tid] = inv; else invk[tid - DC] = inv;
    }
    __syncthreads();

    if (tid < DC) {
        const float t = temperature[h];
        const float iq = invq[tid] * t;
        float m = -INFINITY;
        float row[DC];
        #pragma unroll 8
        for (int d = 0; d < DC; d++) {
            float v = S[tid][d] * iq * invk[d];
            row[d] = v;
            m = fmaxf(m, v);
        }
        float sum = 0.f;
        #pragma unroll 8
        for (int d = 0; d < DC; d++) {
            float e = expf(row[d] - m);
            row[d] = e;
            sum += e;
        }
        float inv = 1.0f / sum;
        uint32_t* oh = (uint32_t*)(ShG + (long long)bh * (DC * DC) + tid * DC);
        #pragma unroll
        for (int d = 0; d < DC; d += 2)
            oh[d / 2] = pack_h2(row[d] * inv, row[d + 1] * inv);
    }
}

// ---------------------------------------------------------------------------
// sv_mma: O = S * V (fp16 1-term, K=48). Coalesced fp16 stores via smem bounce.
// grid = (NCHUNK_SV, B*HD).
// ---------------------------------------------------------------------------
#define SPITCH 56
#define VPITCH 136

__global__ __launch_bounds__(256) void sv_mma_kernel(
    const __half* __restrict__ ShG,
    const __half* __restrict__ vh,
    __half* __restrict__ oh)
{
    __shared__ __align__(16) uint16_t sS[DC * SPITCH];
    __shared__ __align__(16) uint16_t sV[DC * VPITCH];

    const int chunk = blockIdx.x;
    const int bh = blockIdx.y;
    const int b  = bh >> 3;
    const int h  = bh & 7;
    const long long vbase = ((long long)b * KVC + C + h * DC) * HW;
    const long long obase = ((long long)b * C + h * DC) * HW;
    const int sbase = chunk * (HW / NCHUNK_SV);

    const int tid  = threadIdx.x;
    const int warp = tid >> 5;
    const int lane = tid & 31;
    const int lrow  = (lane & 7) + ((lane >> 3) & 1) * 8;
    const int lhalf = lane >> 4;
    const int crow = lane >> 2;
    const int ccol = (lane & 3) * 2;

    const uint32_t uS = smem_u32(sS);
    const uint32_t uV = smem_u32(sV);

    for (int idx = tid; idx < 288; idx += 256) {
        int row = idx / 6, g = idx % 6;
        uint32_t d = (uint32_t)(row * SPITCH + g * 8) * 2;
        cp16(uS + d, ShG + (long long)bh * (DC * DC) + row * DC + g * 8);
    }

    const int n0w = warp * 16;

    for (int it = 0; it < 2; it++) {
        const int s0 = sbase + it * 128;
        #pragma unroll
        for (int i = 0; i < 3; i++) {
            int idx = i * 256 + tid;
            int row = idx >> 4, g = idx & 15;
            uint32_t d = (uint32_t)(row * VPITCH + g * 8) * 2;
            cp16(uV + d, vh + vbase + (long long)row * HW + s0 + g * 8);
        }
        CP_COMMIT();
        CP_WAIT0();
        __syncthreads();

        float acc[24];
        #pragma unroll
        for (int i = 0; i < 24; i++) acc[i] = 0.f;

        #pragma unroll
        for (int ks = 0; ks < 3; ks++) {
            uint32_t bhf[4];
            uint32_t boff = (uint32_t)((ks * 16 + lrow) * VPITCH
                                       + n0w + lhalf * 8) * 2;
            ldsm_x4_t(bhf, uV + boff);
            #pragma unroll
            for (int mt = 0; mt < 3; mt++) {
                uint32_t ah[4];
                uint32_t aoff = (uint32_t)((mt * 16 + lrow) * SPITCH
                                           + ks * 16 + lhalf * 8) * 2;
                ldsm_x4(ah, uS + aoff);
                #pragma unroll
                for (int nt2 = 0; nt2 < 2; nt2++)
                    mma_f16(acc + (mt * 2 + nt2) * 4, ah,
                            bhf[nt2 * 2], bhf[nt2 * 2 + 1]);
            }
        }

        // bounce accumulators through sV for coalesced stores
        __syncthreads();
        #pragma unroll
        for (int mt = 0; mt < 3; mt++) {
            #pragma unroll
            for (int nt2 = 0; nt2 < 2; nt2++) {
                const float* cp = acc + (mt * 2 + nt2) * 4;
                int r0 = mt * 16 + crow;
                int cc = n0w + nt2 * 8 + ccol;
                *(uint32_t*)&sV[r0 * VPITCH + cc]       = pack_h2(cp[0], cp[1]);
                *(uint32_t*)&sV[(r0 + 8) * VPITCH + cc] = pack_h2(cp[2], cp[3]);
            }
        }
        __syncthreads();
        #pragma unroll
        for (int i = 0; i < 3; i++) {
            int idx = i * 256 + tid;          // 48 rows x 16 segs
            int row = idx >> 4, seg = idx & 15;
            uint4 v = *(uint4*)&sV[row * VPITCH + seg * 8];
            *(uint4*)&oh[obase + (long long)row * HW + s0 + seg * 8] = v;
        }
        __syncthreads();
    }
}

// ---------------------------------------------------------------------------
// Launch
// ---------------------------------------------------------------------------
extern "C" void kernel_launch(void* const* d_in, const int* in_sizes, int n_in,
                              void* d_out, int out_size)
{
    const float* x           = (const float*)d_in[0];
    const float* query       = (const float*)d_in[1];
    const float* w_kv        = (const float*)d_in[2];
    const float* w_q         = (const float*)d_in[3];
    const float* w_proj      = (const float*)d_in[4];
    const float* temperature = (const float*)d_in[5];
    float* out = (float*)d_out;

    float *Sp, *ssp;
    cudaGetSymbolAddress((void**)&Sp,  g_Sp);
    cudaGetSymbolAddress((void**)&ssp, g_ssp);

    __half *wkv, *wq, *wp, *xh, *qrh, *kvh, *qh, *oh, *Sh;
    cudaGetSymbolAddress((void**)&wkv,  g_wkv);
    cudaGetSymbolAddress((void**)&wq,   g_wq);
    cudaGetSymbolAddress((void**)&wp,   g_wp);
    cudaGetSymbolAddress((void**)&xh,   g_xh);
    cudaGetSymbolAddress((void**)&qrh,  g_qrh);
    cudaGetSymbolAddress((void**)&kvh,  g_kvh);
    cudaGetSymbolAddress((void**)&qh,   g_qh);
    cudaGetSymbolAddress((void**)&oh,   g_oh);
    cudaGetSymbolAddress((void**)&Sh,   g_Sh);

    cudaFuncSetAttribute(gemm_db_kernel<C, true>,
                         cudaFuncAttributeMaxDynamicSharedMemorySize, SMEM_BYTES);
    cudaFuncSetAttribute(gemm_db_kernel<QC, true>,
                         cudaFuncAttributeMaxDynamicSharedMemorySize, SMEM_BYTES);
    cudaFuncSetAttribute(gemm_db_kernel<C, false>,
                         cudaFuncAttributeMaxDynamicSharedMemorySize, SMEM_BYTES);
    cudaFuncSetAttribute(qk_mma_kernel,
                         cudaFuncAttributeMaxDynamicSharedMemorySize, QK_SMEM);

    // 0) fp32 -> fp16 conversions
    {
        int n4;
        n4 = KVC * C / 4;
        split1_kernel<<<(n4 + 255) / 256, 256>>>(w_kv, wkv, n4);
        n4 = C * QC / 4;
        split1_kernel<<<(n4 + 255) / 256, 256>>>(w_q, wq, n4);
        n4 = C * C / 4;
        split1_kernel<<<(n4 + 255) / 256, 256>>>(w_proj, wp, n4);
        n4 = (int)((long long)B * C * HW / 4);
        split1_kernel<<<(n4 + 255) / 256, 256>>>(x, xh, n4);
        n4 = (int)((long long)B * QC * HW / 4);
        split1_kernel<<<(n4 + 255) / 256, 256>>>(query, qrh, n4);
    }

    // 1) kv = w_kv @ x  -> fp16
    gemm_db_kernel<C, true><<<dim3(HW / 128, KVC / 128, B), 256, SMEM_BYTES>>>(
        wkv, xh, nullptr, kvh, KVC);

    // 2) q = w_q @ query -> fp16
    gemm_db_kernel<QC, true><<<dim3(HW / 128, C / 128, B), 256, SMEM_BYTES>>>(
        wq, qrh, nullptr, qh, C);

    // 3) QK^T partials + sumsq (1-term fp16 MMA)
    qk_mma_kernel<<<dim3(NCHUNK_QK, B * HD), 256, QK_SMEM>>>(
        qh, kvh, Sp, ssp);

    // 4) reduce + norm-scale + softmax -> S fp16
    softmax_kernel<<<B * HD, 256>>>(Sp, ssp, temperature, Sh);

    // 5) O = S * V (1-term fp16 MMA) -> fp16
    sv_mma_kernel<<<dim3(NCHUNK_SV, B * HD), 256>>>(Sh, kvh, oh);

    // 6) out = w_proj @ o -> fp32
    gemm_db_kernel<C, false><<<dim3(HW / 128, C / 128, B), 256, SMEM_BYTES>>>(
        wp, oh, out, nullptr, C);
}